// round 16
// baseline (speedup 1.0000x reference)
#include <cuda_runtime.h>
#include <cuda_fp16.h>
#include <cstdint>

#define L_SEQ   4096
#define B_SZ    4
#define D_MODEL 512
#define D_INNER 1024
#define D_XZ    2048
#define NTOK    (B_SZ*L_SEQ)   /* 16384 */
#define DT_RANK 32
#define D_STATE 16
#define NCH     32              /* time chunks for parallel scan */
#define TCH     (L_SEQ/NCH)     /* 128 steps per chunk */

// ---------------- scratch (static device allocations) -------------------------------
__device__ float g_xz  [(size_t)NTOK*D_XZ];
__device__ float g_axz [(size_t)NTOK*D_XZ];
__device__ float g_u   [3][(size_t)NTOK*D_INNER];      // dt = softplus(logits) (fp32)
__device__ float g_dbl [3][(size_t)NTOK*64];           // dt_low | B | C (fp32 for scan)
__device__ float g_y   [2][(size_t)NTOK*D_INNER];      // f,r branch outputs
// chunked-scan carries
__device__ float g_hend  [3][(size_t)B_SZ*NCH*D_INNER*16];
__device__ float g_hstart[3][(size_t)B_SZ*NCH*D_INNER*16];
__device__ float g_ssum  [3][(size_t)B_SZ*NCH*D_INNER];
// interleaved fp16 pairs. A-side rows: [h0,l0,h1,l1,...] (K2=2K halves).
// W-side rows: duplicated [w0,w0,w1,w1,...] (K2 halves).
__device__ __half g_Haug [(size_t)NTOK*2*D_MODEL];
__device__ __half g_AHaug[(size_t)NTOK*2*D_MODEL];
__device__ __half g_Wi16 [(size_t)D_XZ*2*D_MODEL];
__device__ __half g_Wg16 [(size_t)D_XZ*2*D_MODEL];
__device__ __half g_xsaug[3][(size_t)NTOK*2*D_INNER];  // conv+silu x as {hi,lo} pairs
__device__ __half g_Xp16 [3][(size_t)64*2*D_INNER];
__device__ __half g_dtw16[3][(size_t)D_INNER*2*DT_RANK];
__device__ __half g_dblaug[3][(size_t)NTOK*64];        // interleaved pairs of dt_low(32)
__device__ __half g_Wo16 [(size_t)D_MODEL*2*D_INNER];
__device__ __half g_combaug[(size_t)NTOK*2*D_INNER];

__device__ __forceinline__ float sigmoidf_(float x){ return 1.0f/(1.0f+__expf(-x)); }
__device__ __forceinline__ float siluf_(float x){ return x*sigmoidf_(x); }

__device__ __forceinline__ uint32_t smem_u32(const void* p){
    uint32_t a;
    asm("{ .reg .u64 t; cvta.to.shared.u64 t, %1; cvt.u32.u64 %0, t; }" : "=r"(a) : "l"(p));
    return a;
}
__device__ __forceinline__ void cp_async16(uint32_t dst, const void* src){
    asm volatile("cp.async.cg.shared.global [%0], [%1], 16;\n" :: "r"(dst), "l"(src));
}

// ---- packed f32x2 helpers ----------------------------------------------------------
typedef unsigned long long ull;
__device__ __forceinline__ ull pk2(float lo, float hi){
    ull r; asm("mov.b64 %0, {%1,%2};" : "=l"(r) : "f"(lo), "f"(hi)); return r;
}
__device__ __forceinline__ void upk2(ull v, float& lo, float& hi){
    asm("mov.b64 {%0,%1}, %2;" : "=f"(lo), "=f"(hi) : "l"(v));
}
#define F2FMA(d,a,b,c) asm("fma.rn.f32x2 %0, %1, %2, %3;" : "=l"(d) : "l"(a), "l"(b), "l"(c))
#define F2MUL(d,a,b)   asm("mul.rn.f32x2 %0, %1, %2;"     : "=l"(d) : "l"(a), "l"(b))

__device__ __forceinline__ float fast_softplus(float u){
    return (u > 15.f) ? u : __logf(1.f + __expf(u));
}

// ====== prepA: all W converts fp32 [.,K] -> fp16 duplicated-interleave [., 2K] ======
struct CJob { const float* src; __half* dst; int n4; };
struct CJobs9 { CJob j[9]; };
__global__ void convWdup_multi9(CJobs9 J)
{
    const CJob jb = J.j[blockIdx.z];
    const int i = blockIdx.x*256 + threadIdx.x;
    if (i >= jb.n4) return;
    const float4 v = ((const float4*)jb.src)[i];
    __half h0=__float2half_rn(v.x), h1=__float2half_rn(v.y),
           h2=__float2half_rn(v.z), h3=__float2half_rn(v.w);
    __align__(16) __half o[8] = {h0,h0,h1,h1,h2,h2,h3,h3};
    *(uint4*)(jb.dst + (size_t)i*8) = *(const uint4*)o;
}

// ====== prepB: A splits fp32 [R,K] -> fp16 interleaved [R, 2K] = [h,l,h,l,...] ======
struct SJob { const float* src; __half* dst; };
struct SJobs2 { SJob j[2]; int K; int n4; };
__global__ void splitA16_multi(SJobs2 J)
{
    const SJob jb = J.j[blockIdx.z];
    const int i = blockIdx.x*256 + threadIdx.x;
    if (i >= J.n4) return;
    const int kq = J.K >> 2;
    const int r  = i / kq, k4 = i % kq;
    const float4 v = *(const float4*)(jb.src + (size_t)r*J.K + k4*4);
    const float f[4] = {v.x, v.y, v.z, v.w};
    __align__(16) __half o[8];
#pragma unroll
    for (int j=0;j<4;j++){
        const __half hh = __float2half_rn(f[j]);
        o[2*j]   = hh;
        o[2*j+1] = __float2half_rn(f[j] - __half2float(hh));
    }
    *(uint4*)(jb.dst + (size_t)r*2*J.K + (size_t)k4*8) = *(const uint4*)o;
}

// ================= mma.sync fp16 GEMM: BK=64, NS=3, single sync per k-iter ==========
struct MG  { const __half *A, *W; const float* bias; float* C; __half* Daug; };
struct MG3 { MG g[3]; int N, K2; };

template<int BN, bool BIAS, bool DBLAUG, bool SOFTPLUS>
__global__ void __launch_bounds__(256, 2) mma_gemm(MG3 P)
{
    constexpr int NS  = 3;
    constexpr int WN  = BN/2;
    constexpr int NTL = WN/8;
    constexpr int RSTR = 144;                   // bytes per smem row
    constexpr int SA_B = 128*RSTR;
    constexpr int SW_B = BN*RSTR;
    const MG g = P.g[blockIdx.z];
    const int N = P.N, K2 = P.K2;
    const int tid  = threadIdx.x;
    const int lane = tid & 31, wid = tid >> 5;
    const int warp_m = wid & 3, warp_n = wid >> 2;
    const int m0 = blockIdx.y * 128, n0 = blockIdx.x * BN;

    extern __shared__ __align__(128) __half sm[];
    const uint32_t base = smem_u32(sm);
    uint32_t aB[NS], wB[NS];
#pragma unroll
    for (int s=0;s<NS;s++){
        aB[s] = base + (uint32_t)(s*(SA_B+SW_B));
        wB[s] = aB[s] + SA_B;
    }

    float acc[2][NTL][4];
#pragma unroll
    for (int mt=0;mt<2;mt++)
#pragma unroll
        for (int nt=0;nt<NTL;nt++)
#pragma unroll
            for (int j=0;j<4;j++) acc[mt][nt][j]=0.f;

    const int nk = K2 / 64;

    auto load_tiles = [&](int s, int kt){
        const int k0 = kt*64;
        const __half* Ap = g.A + (size_t)m0*K2 + k0;
#pragma unroll
        for (int q = tid; q < 1024; q += 256){
            const int r = q>>3, c = q&7;
            cp_async16(aB[s] + r*RSTR + c*16, Ap + (size_t)r*K2 + c*8);
        }
        const __half* Wp = g.W + (size_t)n0*K2 + k0;
#pragma unroll
        for (int q = tid; q < BN*8; q += 256){
            const int r = q>>3, c = q&7;
            cp_async16(wB[s] + r*RSTR + c*16, Wp + (size_t)r*K2 + c*8);
        }
        asm volatile("cp.async.commit_group;\n" ::: "memory");
    };

#pragma unroll
    for (int s=0; s<NS-1; s++){
        if (s < nk) load_tiles(s, s);
        else asm volatile("cp.async.commit_group;\n" ::: "memory");
    }

    const int lr       = lane & 7;
    const int arow_off = ((lane>>3)&1)*8 + lr;
    const int akb      = (lane>>4)*16;
    const int brow_off = ((lane>>4)&1)*8 + lr;
    const int bkb      = ((lane>>3)&1)*16;

    for (int kt = 0; kt < nk; kt++){
        asm volatile("cp.async.wait_group 1;\n" ::: "memory");
        __syncthreads();
        const int pf = kt + NS - 1;
        if (pf < nk) load_tiles(pf % NS, pf);
        else asm volatile("cp.async.commit_group;\n" ::: "memory");

        const uint32_t aBc = aB[kt % NS], wBc = wB[kt % NS];
#pragma unroll
        for (int ks = 0; ks < 4; ks++){
            uint32_t a[2][4];
#pragma unroll
            for (int mt=0; mt<2; mt++){
                const uint32_t addr = aBc + (warp_m*32 + mt*16 + arow_off)*RSTR + ks*32 + akb;
                asm volatile("ldmatrix.sync.aligned.m8n8.x4.shared.b16 {%0,%1,%2,%3}, [%4];"
                    : "=r"(a[mt][0]),"=r"(a[mt][1]),"=r"(a[mt][2]),"=r"(a[mt][3]) : "r"(addr));
            }
            uint32_t b[NTL][2];
#pragma unroll
            for (int ntp=0; ntp<NTL/2; ntp++){
                const uint32_t addr = wBc + (warp_n*WN + ntp*16 + brow_off)*RSTR + ks*32 + bkb;
                asm volatile("ldmatrix.sync.aligned.m8n8.x4.shared.b16 {%0,%1,%2,%3}, [%4];"
                    : "=r"(b[2*ntp][0]),"=r"(b[2*ntp][1]),
                      "=r"(b[2*ntp+1][0]),"=r"(b[2*ntp+1][1]) : "r"(addr));
            }
#pragma unroll
            for (int mt=0; mt<2; mt++)
#pragma unroll
                for (int nt=0; nt<NTL; nt++){
                    asm volatile("mma.sync.aligned.m16n8k16.row.col.f32.f16.f16.f32 "
                        "{%0,%1,%2,%3}, {%4,%5,%6,%7}, {%8,%9}, {%0,%1,%2,%3};"
                        : "+f"(acc[mt][nt][0]),"+f"(acc[mt][nt][1]),
                          "+f"(acc[mt][nt][2]),"+f"(acc[mt][nt][3])
                        : "r"(a[mt][0]),"r"(a[mt][1]),"r"(a[mt][2]),"r"(a[mt][3]),
                          "r"(b[nt][0]),"r"(b[nt][1]));
                }
        }
    }

    const int lr4 = lane>>2, lc2 = (lane&3)*2;
#pragma unroll
    for (int mt=0; mt<2; mt++){
        const int r0 = m0 + warp_m*32 + mt*16 + lr4;
#pragma unroll
        for (int nt=0; nt<NTL; nt++){
            const int col = n0 + warp_n*WN + nt*8 + lc2;
            float b0=0.f, b1=0.f;
            if (BIAS){ b0 = g.bias[col]; b1 = g.bias[col+1]; }
            float2 v0, v1;
            v0.x = acc[mt][nt][0]+b0; v0.y = acc[mt][nt][1]+b1;
            v1.x = acc[mt][nt][2]+b0; v1.y = acc[mt][nt][3]+b1;
            if (SOFTPLUS){
                v0.x = fast_softplus(v0.x); v0.y = fast_softplus(v0.y);
                v1.x = fast_softplus(v1.x); v1.y = fast_softplus(v1.y);
            }
            *(float2*)(g.C + (size_t)r0*N + col)     = v0;
            *(float2*)(g.C + (size_t)(r0+8)*N + col) = v1;
            if (DBLAUG && col < 32){
                __half2* D0 = (__half2*)(g.Daug + (size_t)r0*64);
                __half2* D1 = (__half2*)(g.Daug + (size_t)(r0+8)*64);
                __half h;
                h = __float2half_rn(v0.x); D0[col]   = __halves2half2(h, __float2half_rn(v0.x - __half2float(h)));
                h = __float2half_rn(v0.y); D0[col+1] = __halves2half2(h, __float2half_rn(v0.y - __half2float(h)));
                h = __float2half_rn(v1.x); D1[col]   = __halves2half2(h, __float2half_rn(v1.x - __half2float(h)));
                h = __float2half_rn(v1.y); D1[col+1] = __halves2half2(h, __float2half_rn(v1.y - __half2float(h)));
            }
        }
    }
}

// -------- merged conv, 2 channels/thread: z=0 fused f+r on xz; z=1 g on axz ---------
struct ConvAll {
    const float* Xfr; const float* wf; const float* bf;
    const float* wr;  const float* br;
    __half2* xf; __half2* xr;
    const float* Xg; const float* wg; const float* bg; __half2* xg;
};
#define CCH2 64

__device__ __forceinline__ __half2 mk_pair(float s){
    const __half hh = __float2half_rn(s);
    return __halves2half2(hh, __float2half_rn(s - __half2float(hh)));
}

__global__ void conv_all_kernel(ConvAll P)
{
    const int d0 = (blockIdx.x*128 + threadIdx.x)*2;   // channel pair
    const int bt = blockIdx.y;                          // 0..255
    const int b  = bt >> 6;
    const int t0 = (bt & 63)*CCH2;
    const size_t bL = (size_t)b*L_SEQ;

    if (blockIdx.z == 0){
        const float4 wfA = *(const float4*)(P.wf + d0*4);
        const float4 wfB = *(const float4*)(P.wf + d0*4 + 4);
        const float4 wrA = *(const float4*)(P.wr + d0*4);
        const float4 wrB = *(const float4*)(P.wr + d0*4 + 4);
        const float bfA = P.bf[d0], bfB = P.bf[d0+1];
        const float brA = P.br[d0], brB = P.br[d0+1];
        auto X2 = [&](int i)->float2{
            if (i < 0 || i >= L_SEQ) return make_float2(0.f, 0.f);
            return *(const float2*)(P.Xfr + (bL + i)*(size_t)D_XZ + d0);
        };
        float2 xw[7];
#pragma unroll
        for (int j=0;j<6;j++) xw[j] = X2(t0-3+j);
#pragma unroll 4
        for (int t=t0; t<t0+CCH2; t++){
            xw[6] = X2(t+3);
            const float vfA = fmaf(wfA.x,xw[0].x,fmaf(wfA.y,xw[1].x,fmaf(wfA.z,xw[2].x,fmaf(wfA.w,xw[3].x,bfA))));
            const float vfB = fmaf(wfB.x,xw[0].y,fmaf(wfB.y,xw[1].y,fmaf(wfB.z,xw[2].y,fmaf(wfB.w,xw[3].y,bfB))));
            const float vrA = fmaf(wrA.x,xw[6].x,fmaf(wrA.y,xw[5].x,fmaf(wrA.z,xw[4].x,fmaf(wrA.w,xw[3].x,brA))));
            const float vrB = fmaf(wrB.x,xw[6].y,fmaf(wrB.y,xw[5].y,fmaf(wrB.z,xw[4].y,fmaf(wrB.w,xw[3].y,brB))));
            __align__(8) __half2 of[2] = { mk_pair(siluf_(vfA)), mk_pair(siluf_(vfB)) };
            __align__(8) __half2 orr[2] = { mk_pair(siluf_(vrA)), mk_pair(siluf_(vrB)) };
            *(uint2*)(P.xf + (bL+t)*(size_t)D_INNER + d0) = *(const uint2*)of;
            *(uint2*)(P.xr + (bL + (L_SEQ-1-t))*(size_t)D_INNER + d0) = *(const uint2*)orr;
#pragma unroll
            for (int j=0;j<6;j++) xw[j]=xw[j+1];
        }
    } else {
        const float4 wgA = *(const float4*)(P.wg + d0*4);
        const float4 wgB = *(const float4*)(P.wg + d0*4 + 4);
        const float bgA = P.bg[d0], bgB = P.bg[d0+1];
        auto X2 = [&](int i)->float2{
            if (i < 0) return make_float2(0.f, 0.f);
            return *(const float2*)(P.Xg + (bL + i)*(size_t)D_XZ + d0);
        };
        float2 x0=X2(t0-3), x1=X2(t0-2), x2=X2(t0-1);
#pragma unroll 4
        for (int t=t0; t<t0+CCH2; t++){
            const float2 x3 = X2(t);
            const float vA = fmaf(wgA.x,x0.x,fmaf(wgA.y,x1.x,fmaf(wgA.z,x2.x,fmaf(wgA.w,x3.x,bgA))));
            const float vB = fmaf(wgB.x,x0.y,fmaf(wgB.y,x1.y,fmaf(wgB.z,x2.y,fmaf(wgB.w,x3.y,bgB))));
            __align__(8) __half2 og[2] = { mk_pair(siluf_(vA)), mk_pair(siluf_(vB)) };
            *(uint2*)(P.xg + (bL+t)*(size_t)D_INNER + d0) = *(const uint2*)og;
            x0=x1; x1=x2; x2=x3;
        }
    }
}

// ============== chunked selective scan (dt precomputed in dtproj epilogue) ==========
struct ScanB { const float* U; const __half2* XS2; const float* DBL; const float* XZb;
               const float* Alog; const float* Dp; float* Y;
               float* Hend; float* Hstart; float* Ssum; int rev; };
struct ScanB3 { ScanB s[3]; };

__device__ __forceinline__ void load_A16(const float* Alog, int d, float* a,
                                         float& a0, bool& pw){
#pragma unroll
    for (int n=0;n<16;n++) a[n] = -__expf(Alog[d*16+n]);
    a0 = a[0];
    pw = fabsf(a0) > 1e-20f;
#pragma unroll
    for (int n=0;n<16;n++){
        const float r = a[n]/a0;
        pw = pw && (fabsf(r - (float)(n+1)) < 1e-4f);
    }
}

// Phase A: per-chunk local scan from h=0; stores h_end and S=Σdt. grid(8, B*NCH, 3)
__global__ void scanA_kernel(ScanB3 P)
{
    __shared__ float sB[TCH][16];
    const ScanB S = P.s[blockIdx.z];
    const int tid = threadIdx.x;
    const int d   = blockIdx.x*128 + tid;
    const int b   = blockIdx.y >> 5;
    const int ch  = blockIdx.y & (NCH-1);
    const size_t bL = (size_t)b*L_SEQ;
    const int t0 = ch*TCH;

    float a[16], a0; bool pw;
    load_A16(S.Alog, d, a, a0, pw);

#pragma unroll
    for (int r=0;r<(TCH*16)/(4*128);r++){
        const int slot = tid + r*128;
        const int tt = slot>>2, q = slot&3;
        const float4 v = *(const float4*)(S.DBL + (bL + t0 + tt)*64 + 32 + q*4);
        *(float4*)&sB[tt][q*4] = v;
    }
    __syncthreads();

    __align__(16) float h[16];
#pragma unroll
    for (int n=0;n<16;n++) h[n]=0.f;
    ull* h2 = (ull*)h;
    float Ss = 0.f;

#pragma unroll 2
    for (int tt=0;tt<TCH;tt++){
        const size_t idx = (bL + t0 + tt)*(size_t)D_INNER + d;
        const float dt = S.U[idx];                 // already softplus'd
        const __half2 xp = S.XS2[idx];
        const float xv = __half2float(__low2half(xp)) + __half2float(__high2half(xp));
        Ss += dt;
        const float dtx = dt*xv;
        if (pw){
            const float p  = __expf(dt*a0);
            const float p2 = p*p;
            ull ep = pk2(p, p2);
            const ull estep = pk2(p2, p2);
            const ull dtx2  = pk2(dtx, dtx);
            const ull* Bp = (const ull*)&sB[tt][0];
#pragma unroll
            for (int k=0;k<8;k++){
                ull t1; F2MUL(t1, dtx2, Bp[k]);
                F2FMA(h2[k], ep, h2[k], t1);
                if (k<7) F2MUL(ep, ep, estep);
            }
        } else {
#pragma unroll
            for (int n=0;n<16;n++){
                const float e = __expf(dt*a[n]);
                h[n] = fmaf(e, h[n], dtx*sB[tt][n]);
            }
        }
    }
    float* He = S.Hend + ((size_t)(b*NCH + ch)*D_INNER + d)*16;
#pragma unroll
    for (int q=0;q<4;q++) *(float4*)(He + q*4) = *(float4*)&h[q*4];
    S.Ssum[(size_t)(b*NCH + ch)*D_INNER + d] = Ss;
}

// Phase B: prefix over chunks. grid(8, B, 3), 128 threads
__global__ void scanB_kernel(ScanB3 P)
{
    const ScanB S = P.s[blockIdx.z];
    const int tid = threadIdx.x;
    const int d   = blockIdx.x*128 + tid;
    const int b   = blockIdx.y;

    float a[16], a0; bool pw;
    load_A16(S.Alog, d, a, a0, pw);

    __align__(16) float hs[16];
#pragma unroll
    for (int n=0;n<16;n++) hs[n]=0.f;
    ull* hs2 = (ull*)hs;

    for (int c=0;c<NCH;c++){
        const size_t off = ((size_t)(b*NCH + c)*D_INNER + d)*16;
        float* Hs = S.Hstart + off;
#pragma unroll
        for (int q=0;q<4;q++) *(float4*)(Hs + q*4) = *(float4*)&hs[q*4];
        const float Sc = S.Ssum[(size_t)(b*NCH + c)*D_INNER + d];
        const float* He = S.Hend + off;
        __align__(16) float he[16];
#pragma unroll
        for (int q=0;q<4;q++) *(float4*)&he[q*4] = *(const float4*)(He + q*4);
        if (pw){
            const float p  = __expf(Sc*a0);
            const float p2 = p*p;
            ull ep = pk2(p, p2);
            const ull estep = pk2(p2, p2);
            const ull* he2 = (const ull*)he;
#pragma unroll
            for (int k=0;k<8;k++){
                F2FMA(hs2[k], ep, hs2[k], he2[k]);
                if (k<7) F2MUL(ep, ep, estep);
            }
        } else {
#pragma unroll
            for (int n=0;n<16;n++){
                const float e = __expf(Sc*a[n]);
                hs[n] = fmaf(e, hs[n], he[n]);
            }
        }
    }
}

// Phase C (f, r branches): re-run chunk from true h_start, emit gated y. grid(8, B*NCH, 2)
__global__ void scanC_kernel(ScanB3 P)
{
    __shared__ float sBC[TCH][32];
    const ScanB S = P.s[blockIdx.z];
    const int tid = threadIdx.x;
    const int d   = blockIdx.x*128 + tid;
    const int b   = blockIdx.y >> 5;
    const int ch  = blockIdx.y & (NCH-1);
    const size_t bL = (size_t)b*L_SEQ;
    const int t0 = ch*TCH;

    float a[16], a0; bool pw;
    load_A16(S.Alog, d, a, a0, pw);
    const float Dd = S.Dp[d];

    __align__(16) float h[16];
    {
        const float* Hs = S.Hstart + ((size_t)(b*NCH + ch)*D_INNER + d)*16;
#pragma unroll
        for (int q=0;q<4;q++) *(float4*)&h[q*4] = *(const float4*)(Hs + q*4);
    }
    ull* h2 = (ull*)h;

#pragma unroll
    for (int r=0;r<(TCH*32)/(4*128);r++){
        const int slot = tid + r*128;
        const int tt = slot>>3, q = slot&7;
        const float4 v = *(const float4*)(S.DBL + (bL + t0 + tt)*64 + 32 + q*4);
        *(float4*)&sBC[tt][q*4] = v;
    }
    __syncthreads();

#pragma unroll 2
    for (int tt=0;tt<TCH;tt++){
        const int t = t0+tt;
        const size_t idx = (bL + t)*(size_t)D_INNER + d;
        const float dt = S.U[idx];                 // already softplus'd
        const __half2 xp = S.XS2[idx];
        const float xv = __half2float(__low2half(xp)) + __half2float(__high2half(xp));
        const int lz = S.rev ? (L_SEQ-1-t) : t;
        const float zv = S.XZb[(bL+lz)*(size_t)D_XZ + D_INNER + d];
        const float dtx = dt*xv;
        float y;
        if (pw){
            const float p  = __expf(dt*a0);
            const float p2 = p*p;
            ull ep = pk2(p, p2);
            const ull estep = pk2(p2, p2);
            const ull dtx2  = pk2(dtx, dtx);
            const ull* Bp = (const ull*)&sBC[tt][0];
            const ull* Cp = (const ull*)&sBC[tt][16];
            ull ya0 = 0ull, ya1 = 0ull;
#pragma unroll
            for (int k=0;k<8;k++){
                ull t1; F2MUL(t1, dtx2, Bp[k]);
                F2FMA(h2[k], ep, h2[k], t1);
                if (k & 1) { F2FMA(ya1, h2[k], Cp[k], ya1); }
                else       { F2FMA(ya0, h2[k], Cp[k], ya0); }
                if (k<7) F2MUL(ep, ep, estep);
            }
            float s0,s1,s2,s3;
            upk2(ya0, s0, s1); upk2(ya1, s2, s3);
            y = (s0+s1) + (s2+s3);
        } else {
            float ya[4] = {0.f,0.f,0.f,0.f};
#pragma unroll
            for (int n=0;n<16;n++){
                const float e = __expf(dt*a[n]);
                h[n] = fmaf(e, h[n], dtx*sBC[tt][n]);
                ya[n&3] = fmaf(h[n], sBC[tt][16+n], ya[n&3]);
            }
            y = (ya[0]+ya[1]) + (ya[2]+ya[3]);
        }
        S.Y[idx] = (y + Dd*xv) * siluf_(zv);
    }
}

// Phase C for g branch + fused combine: emits combaug directly. grid(8, B*NCH)
struct ScanCG { const float* U; const __half2* XS2; const float* DBL; const float* XZb;
                const float* Alog; const float* Dp; const float* Hstart;
                const float* Yf; const float* Yr; __half2* Cout; };

__global__ void scanCg_combine_kernel(ScanCG S)
{
    __shared__ float sBC[TCH][32];
    const int tid = threadIdx.x;
    const int d   = blockIdx.x*128 + tid;
    const int b   = blockIdx.y >> 5;
    const int ch  = blockIdx.y & (NCH-1);
    const size_t bL = (size_t)b*L_SEQ;
    const int t0 = ch*TCH;

    float a[16], a0; bool pw;
    load_A16(S.Alog, d, a, a0, pw);
    const float Dd = S.Dp[d];

    __align__(16) float h[16];
    {
        const float* Hs = S.Hstart + ((size_t)(b*NCH + ch)*D_INNER + d)*16;
#pragma unroll
        for (int q=0;q<4;q++) *(float4*)&h[q*4] = *(const float4*)(Hs + q*4);
    }
    ull* h2 = (ull*)h;

#pragma unroll
    for (int r=0;r<(TCH*32)/(4*128);r++){
        const int slot = tid + r*128;
        const int tt = slot>>3, q = slot&7;
        const float4 v = *(const float4*)(S.DBL + (bL + t0 + tt)*64 + 32 + q*4);
        *(float4*)&sBC[tt][q*4] = v;
    }
    __syncthreads();

#pragma unroll 2
    for (int tt=0;tt<TCH;tt++){
        const int t = t0+tt;
        const size_t idx = (bL + t)*(size_t)D_INNER + d;
        const float dt = S.U[idx];
        const __half2 xp = S.XS2[idx];
        const float xv = __half2float(__low2half(xp)) + __half2float(__high2half(xp));
        const float zv = S.XZb[(bL+t)*(size_t)D_XZ + D_INNER + d];
        const float dtx = dt*xv;
        float y;
        if (pw){
            const float p  = __expf(dt*a0);
            const float p2 = p*p;
            ull ep = pk2(p, p2);
            const ull estep = pk2(p2, p2);
            const ull dtx2  = pk2(dtx, dtx);
            const ull* Bp = (const ull*)&sBC[tt][0];
            const ull* Cp = (const ull*)&sBC[tt][16];
            ull ya0 = 0ull, ya1 = 0ull;
#pragma unroll
            for (int k=0;k<8;k++){
                ull t1; F2MUL(t1, dtx2, Bp[k]);
                F2FMA(h2[k], ep, h2[k], t1);
                if (k & 1) { F2FMA(ya1, h2[k], Cp[k], ya1); }
                else       { F2FMA(ya0, h2[k], Cp[k], ya0); }
                if (k<7) F2MUL(ep, ep, estep);
            }
            float s0,s1,s2,s3;
            upk2(ya0, s0, s1); upk2(ya1, s2, s3);
            y = (s0+s1) + (s2+s3);
        } else {
            float ya[4] = {0.f,0.f,0.f,0.f};
#pragma unroll
            for (int n=0;n<16;n++){
                const float e = __expf(dt*a[n]);
                h[n] = fmaf(e, h[n], dtx*sBC[tt][n]);
                ya[n&3] = fmaf(h[n], sBC[tt][16+n], ya[n&3]);
            }
            y = (ya[0]+ya[1]) + (ya[2]+ya[3]);
        }
        const float yg = (y + Dd*xv) * siluf_(zv);     // g-branch gated output
        // fused combine: (yf + flip(yr)) * silu(yg)
        const float yfv = S.Yf[idx];
        const float yrv = S.Yr[(bL + (L_SEQ-1-t))*(size_t)D_INNER + d];
        const float v = (yfv + yrv) * siluf_(yg);
        const __half hh = __float2half_rn(v);
        S.Cout[(bL+t)*(size_t)D_INNER + d] =
            __halves2half2(hh, __float2half_rn(v - __half2float(hh)));
    }
}

// ------------------------------- host driver ----------------------------------------
extern "C" void kernel_launch(void* const* d_in, const int* in_sizes, int n_in,
                              void* d_out, int out_size)
{
    const float* H    = (const float*)d_in[0];
    const float* AH   = (const float*)d_in[1];
    const float* Winp = (const float*)d_in[2];
    const float* Wing = (const float*)d_in[3];
    const float* convw[3] = { (const float*)d_in[4], (const float*)d_in[6], (const float*)d_in[8] };
    const float* convb[3] = { (const float*)d_in[5], (const float*)d_in[7], (const float*)d_in[9] };
    const float* xproj[3] = { (const float*)d_in[10], (const float*)d_in[11], (const float*)d_in[12] };
    const float* dtw[3]   = { (const float*)d_in[13], (const float*)d_in[15], (const float*)d_in[17] };
    const float* dtb[3]   = { (const float*)d_in[14], (const float*)d_in[16], (const float*)d_in[18] };
    const float* Alog[3]  = { (const float*)d_in[19], (const float*)d_in[20], (const float*)d_in[21] };
    const float* Dp[3]    = { (const float*)d_in[22], (const float*)d_in[23], (const float*)d_in[24] };
    const float* Wout = (const float*)d_in[25];
    float* out = (float*)d_out;

    float *p_xz, *p_axz, *p_u, *p_dbl, *p_y, *p_hend, *p_hstart, *p_ssum;
    __half *p_Haug, *p_AHaug, *p_Wi16, *p_Wg16, *p_xsaug, *p_Xp16;
    __half *p_dtw16, *p_dblaug, *p_Wo16, *p_combaug;
    cudaGetSymbolAddress((void**)&p_xz,     g_xz);
    cudaGetSymbolAddress((void**)&p_axz,    g_axz);
    cudaGetSymbolAddress((void**)&p_u,      g_u);
    cudaGetSymbolAddress((void**)&p_dbl,    g_dbl);
    cudaGetSymbolAddress((void**)&p_y,      g_y);
    cudaGetSymbolAddress((void**)&p_hend,   g_hend);
    cudaGetSymbolAddress((void**)&p_hstart, g_hstart);
    cudaGetSymbolAddress((void**)&p_ssum,   g_ssum);
    cudaGetSymbolAddress((void**)&p_Haug,   g_Haug);
    cudaGetSymbolAddress((void**)&p_AHaug,  g_AHaug);
    cudaGetSymbolAddress((void**)&p_Wi16,   g_Wi16);
    cudaGetSymbolAddress((void**)&p_Wg16,   g_Wg16);
    cudaGetSymbolAddress((void**)&p_xsaug,  g_xsaug);
    cudaGetSymbolAddress((void**)&p_Xp16,   g_Xp16);
    cudaGetSymbolAddress((void**)&p_dtw16,  g_dtw16);
    cudaGetSymbolAddress((void**)&p_dblaug, g_dblaug);
    cudaGetSymbolAddress((void**)&p_Wo16,   g_Wo16);
    cudaGetSymbolAddress((void**)&p_combaug,g_combaug);

    const size_t SXS   = (size_t)NTOK*D_INNER;
    const size_t SDBL  = (size_t)NTOK*64;
    const size_t SXSA  = (size_t)NTOK*2*D_INNER;
    const size_t SXP   = (size_t)64*2*D_INNER;
    const size_t SDTW  = (size_t)D_INNER*2*DT_RANK;
    const size_t SDBLA = (size_t)NTOK*64;
    const size_t SHE   = (size_t)B_SZ*NCH*D_INNER*16;
    const size_t SSS   = (size_t)B_SZ*NCH*D_INNER;

    const int SMEM128 = 3*(128+128)*144;   // 110592 B
    const int SMEM64  = 3*(128+ 64)*144;   //  82944 B
    cudaFuncSetAttribute((const void*)mma_gemm<128,false,false,false>, cudaFuncAttributeMaxDynamicSharedMemorySize, SMEM128);
    cudaFuncSetAttribute((const void*)mma_gemm<128,true,false,true>,   cudaFuncAttributeMaxDynamicSharedMemorySize, SMEM128);
    cudaFuncSetAttribute((const void*)mma_gemm<64,false,true,false>,   cudaFuncAttributeMaxDynamicSharedMemorySize, SMEM64);
    cudaFuncSetAttribute((const void*)mma_gemm<64,false,false,false>,  cudaFuncAttributeMaxDynamicSharedMemorySize, SMEM64);

    // #1: ALL weight conversions (9 jobs, one launch)
    {
        CJobs9 J;
        J.j[0] = { Winp, p_Wi16, (int)((size_t)D_XZ*D_MODEL/4) };
        J.j[1] = { Wing, p_Wg16, (int)((size_t)D_XZ*D_MODEL/4) };
        for (int z=0; z<3; z++){
            J.j[2+z] = { xproj[z], p_Xp16  + z*SXP,  (int)((size_t)64*D_INNER/4) };
            J.j[5+z] = { dtw[z],   p_dtw16 + z*SDTW, (int)((size_t)D_INNER*DT_RANK/4) };
        }
        J.j[8] = { Wout, p_Wo16, (int)((size_t)D_MODEL*D_INNER/4) };
        const int maxb = ((int)((size_t)D_XZ*D_MODEL/4) + 255)/256;   // 1024
        convWdup_multi9<<<dim3(maxb,1,9), 256>>>(J);
    }
    // #2: both activation splits (H, AH) in one launch
    {
        SJobs2 J;
        J.j[0] = { H,  p_Haug };
        J.j[1] = { AH, p_AHaug };
        J.K = D_MODEL; J.n4 = NTOK*D_MODEL/4;
        splitA16_multi<<<dim3((J.n4+255)/256,1,2), 256>>>(J);
    }
    // #3: in-projections
    {
        MG3 P; P.N = D_XZ; P.K2 = 2*D_MODEL;
        P.g[0] = { p_Haug,  p_Wi16, nullptr, p_xz,  nullptr };
        P.g[1] = { p_AHaug, p_Wg16, nullptr, p_axz, nullptr };
        P.g[2] = P.g[0];
        mma_gemm<128,false,false,false><<<dim3(D_XZ/128, NTOK/128, 2), 256, SMEM128>>>(P);
    }
    // #4: ALL convs, 2 channels/thread  <-- ncu profile slot
    {
        ConvAll P = { p_xz, convw[0], convb[0], convw[1], convb[1],
                      (__half2*)(p_xsaug + 0*SXSA), (__half2*)(p_xsaug + 1*SXSA),
                      p_axz, convw[2], convb[2], (__half2*)(p_xsaug + 2*SXSA) };
        conv_all_kernel<<<dim3(D_INNER/256, B_SZ*(L_SEQ/CCH2), 2), 128>>>(P);
    }
    // #5: x-projection (fused dblaug epilogue)
    {
        MG3 P; P.N = 64; P.K2 = 2*D_INNER;
        for (int z=0; z<3; z++)
            P.g[z] = { p_xsaug + z*SXSA, p_Xp16 + z*SXP, nullptr, p_dbl + z*SDBL, p_dblaug + z*SDBLA };
        mma_gemm<64,false,true,false><<<dim3(1, NTOK/128, 3), 256, SMEM64>>>(P);
    }
    // #6: dt-projection (softplus fused in epilogue -> stores dt directly)
    {
        MG3 P; P.N = D_INNER; P.K2 = 2*DT_RANK;
        for (int z=0; z<3; z++)
            P.g[z] = { p_dblaug + z*SDBLA, p_dtw16 + z*SDTW, dtb[z], p_u + z*SXS, nullptr };
        mma_gemm<128,true,false,true><<<dim3(D_INNER/128, NTOK/128, 3), 256, SMEM128>>>(P);
    }
    // #7-#10: chunked selective scan; scanC for f,r; scanCg fuses g + combine
    {
        ScanB3 P;
        P.s[0] = { p_u + 0*SXS, (const __half2*)(p_xsaug + 0*SXSA), p_dbl + 0*SDBL, p_xz,
                   Alog[0], Dp[0], p_y + 0*SXS, p_hend + 0*SHE, p_hstart + 0*SHE, p_ssum + 0*SSS, 0 };
        P.s[1] = { p_u + 1*SXS, (const __half2*)(p_xsaug + 1*SXSA), p_dbl + 1*SDBL, p_xz,
                   Alog[1], Dp[1], p_y + 1*SXS, p_hend + 1*SHE, p_hstart + 1*SHE, p_ssum + 1*SSS, 1 };
        P.s[2] = { p_u + 2*SXS, (const __half2*)(p_xsaug + 2*SXSA), p_dbl + 2*SDBL, p_axz,
                   Alog[2], Dp[2], nullptr, p_hend + 2*SHE, p_hstart + 2*SHE, p_ssum + 2*SSS, 0 };
        scanA_kernel<<<dim3(D_INNER/128, B_SZ*NCH, 3), 128>>>(P);
        scanB_kernel<<<dim3(D_INNER/128, B_SZ, 3), 128>>>(P);
        scanC_kernel<<<dim3(D_INNER/128, B_SZ*NCH, 2), 128>>>(P);
        ScanCG G = { p_u + 2*SXS, (const __half2*)(p_xsaug + 2*SXSA), p_dbl + 2*SDBL, p_axz,
                     Alog[2], Dp[2], p_hstart + 2*SHE,
                     p_y + 0*SXS, p_y + 1*SXS, (__half2*)p_combaug };
        scanCg_combine_kernel<<<dim3(D_INNER/128, B_SZ*NCH), 128>>>(G);
    }
    // #11: out-projection (BN=64)
    {
        MG3 P; P.N = D_MODEL; P.K2 = 2*D_INNER;
        P.g[0] = { p_combaug, p_Wo16, nullptr, out, nullptr };
        P.g[1] = P.g[0]; P.g[2] = P.g[0];
        mma_gemm<64,false,false,false><<<dim3(D_MODEL/64, NTOK/128, 1), 256, SMEM64>>>(P);
    }
    (void)in_sizes; (void)n_in; (void)out_size;
}

// round 17
// speedup vs baseline: 1.1255x; 1.1255x over previous
#include <cuda_runtime.h>
#include <cuda_fp16.h>
#include <cstdint>

#define L_SEQ   4096
#define B_SZ    4
#define D_MODEL 512
#define D_INNER 1024
#define D_XZ    2048
#define NTOK    (B_SZ*L_SEQ)   /* 16384 */
#define DT_RANK 32
#define D_STATE 16
#define NCH     32              /* time chunks for parallel scan */
#define TCH     (L_SEQ/NCH)     /* 128 steps per chunk */

// ---------------- scratch (static device allocations) -------------------------------
__device__ float g_xz  [(size_t)NTOK*D_XZ];
__device__ float g_axz [(size_t)NTOK*D_XZ];
__device__ float g_u   [3][(size_t)NTOK*D_INNER];      // dt = softplus(logits) (fp32)
__device__ float g_dbl [3][(size_t)NTOK*64];           // dt_low | B | C (fp32 for scan)
__device__ float g_y   [3][(size_t)NTOK*D_INNER];      // branch outputs
// chunked-scan carries
__device__ float g_hend  [3][(size_t)B_SZ*NCH*D_INNER*16];
__device__ float g_hstart[3][(size_t)B_SZ*NCH*D_INNER*16];
__device__ float g_ssum  [3][(size_t)B_SZ*NCH*D_INNER];
// interleaved fp16 pairs. A-side rows: [h0,l0,h1,l1,...] (K2=2K halves).
// W-side rows: duplicated [w0,w0,w1,w1,...] (K2 halves).
__device__ __half g_Haug [(size_t)NTOK*2*D_MODEL];
__device__ __half g_AHaug[(size_t)NTOK*2*D_MODEL];
__device__ __half g_Wi16 [(size_t)D_XZ*2*D_MODEL];
__device__ __half g_Wg16 [(size_t)D_XZ*2*D_MODEL];
__device__ __half g_xsaug[3][(size_t)NTOK*2*D_INNER];  // conv+silu x as {hi,lo} pairs
__device__ __half g_Xp16 [3][(size_t)64*2*D_INNER];
__device__ __half g_dtw16[3][(size_t)D_INNER*2*DT_RANK];
__device__ __half g_dblaug[3][(size_t)NTOK*64];        // interleaved pairs of dt_low(32)
__device__ __half g_Wo16 [(size_t)D_MODEL*2*D_INNER];
__device__ __half g_combaug[(size_t)NTOK*2*D_INNER];

__device__ __forceinline__ float sigmoidf_(float x){ return 1.0f/(1.0f+__expf(-x)); }
__device__ __forceinline__ float siluf_(float x){ return x*sigmoidf_(x); }

__device__ __forceinline__ uint32_t smem_u32(const void* p){
    uint32_t a;
    asm("{ .reg .u64 t; cvta.to.shared.u64 t, %1; cvt.u32.u64 %0, t; }" : "=r"(a) : "l"(p));
    return a;
}
__device__ __forceinline__ void cp_async16(uint32_t dst, const void* src){
    asm volatile("cp.async.cg.shared.global [%0], [%1], 16;\n" :: "r"(dst), "l"(src));
}

// ---- packed f32x2 helpers ----------------------------------------------------------
typedef unsigned long long ull;
__device__ __forceinline__ ull pk2(float lo, float hi){
    ull r; asm("mov.b64 %0, {%1,%2};" : "=l"(r) : "f"(lo), "f"(hi)); return r;
}
__device__ __forceinline__ void upk2(ull v, float& lo, float& hi){
    asm("mov.b64 {%0,%1}, %2;" : "=f"(lo), "=f"(hi) : "l"(v));
}
#define F2FMA(d,a,b,c) asm("fma.rn.f32x2 %0, %1, %2, %3;" : "=l"(d) : "l"(a), "l"(b), "l"(c))
#define F2MUL(d,a,b)   asm("mul.rn.f32x2 %0, %1, %2;"     : "=l"(d) : "l"(a), "l"(b))

__device__ __forceinline__ float fast_softplus(float u){
    return (u > 15.f) ? u : __logf(1.f + __expf(u));
}

// ====== prepA: all W converts fp32 [.,K] -> fp16 duplicated-interleave [., 2K] ======
struct CJob { const float* src; __half* dst; int n4; };
struct CJobs9 { CJob j[9]; };
__global__ void convWdup_multi9(CJobs9 J)
{
    const CJob jb = J.j[blockIdx.z];
    const int i = blockIdx.x*256 + threadIdx.x;
    if (i >= jb.n4) return;
    const float4 v = ((const float4*)jb.src)[i];
    __half h0=__float2half_rn(v.x), h1=__float2half_rn(v.y),
           h2=__float2half_rn(v.z), h3=__float2half_rn(v.w);
    __align__(16) __half o[8] = {h0,h0,h1,h1,h2,h2,h3,h3};
    *(uint4*)(jb.dst + (size_t)i*8) = *(const uint4*)o;
}

// ====== prepB: A splits fp32 [R,K] -> fp16 interleaved [R, 2K] = [h,l,h,l,...] ======
struct SJob { const float* src; __half* dst; };
struct SJobs2 { SJob j[2]; int K; int n4; };
__global__ void splitA16_multi(SJobs2 J)
{
    const SJob jb = J.j[blockIdx.z];
    const int i = blockIdx.x*256 + threadIdx.x;
    if (i >= J.n4) return;
    const int kq = J.K >> 2;
    const int r  = i / kq, k4 = i % kq;
    const float4 v = *(const float4*)(jb.src + (size_t)r*J.K + k4*4);
    const float f[4] = {v.x, v.y, v.z, v.w};
    __align__(16) __half o[8];
#pragma unroll
    for (int j=0;j<4;j++){
        const __half hh = __float2half_rn(f[j]);
        o[2*j]   = hh;
        o[2*j+1] = __float2half_rn(f[j] - __half2float(hh));
    }
    *(uint4*)(jb.dst + (size_t)r*2*J.K + (size_t)k4*8) = *(const uint4*)o;
}

// ================= mma.sync fp16 GEMM: BK=64, NS=3, single sync per k-iter ==========
struct MG  { const __half *A, *W; const float* bias; float* C; __half* Daug; };
struct MG3 { MG g[3]; int N, K2; };

template<int BN, bool BIAS, bool DBLAUG, bool SOFTPLUS>
__global__ void __launch_bounds__(256, 2) mma_gemm(MG3 P)
{
    constexpr int NS  = 3;
    constexpr int WN  = BN/2;
    constexpr int NTL = WN/8;
    constexpr int RSTR = 144;                   // bytes per smem row
    constexpr int SA_B = 128*RSTR;
    constexpr int SW_B = BN*RSTR;
    const MG g = P.g[blockIdx.z];
    const int N = P.N, K2 = P.K2;
    const int tid  = threadIdx.x;
    const int lane = tid & 31, wid = tid >> 5;
    const int warp_m = wid & 3, warp_n = wid >> 2;
    const int m0 = blockIdx.y * 128, n0 = blockIdx.x * BN;

    extern __shared__ __align__(128) __half sm[];
    const uint32_t base = smem_u32(sm);
    uint32_t aB[NS], wB[NS];
#pragma unroll
    for (int s=0;s<NS;s++){
        aB[s] = base + (uint32_t)(s*(SA_B+SW_B));
        wB[s] = aB[s] + SA_B;
    }

    float acc[2][NTL][4];
#pragma unroll
    for (int mt=0;mt<2;mt++)
#pragma unroll
        for (int nt=0;nt<NTL;nt++)
#pragma unroll
            for (int j=0;j<4;j++) acc[mt][nt][j]=0.f;

    const int nk = K2 / 64;

    auto load_tiles = [&](int s, int kt){
        const int k0 = kt*64;
        const __half* Ap = g.A + (size_t)m0*K2 + k0;
#pragma unroll
        for (int q = tid; q < 1024; q += 256){
            const int r = q>>3, c = q&7;
            cp_async16(aB[s] + r*RSTR + c*16, Ap + (size_t)r*K2 + c*8);
        }
        const __half* Wp = g.W + (size_t)n0*K2 + k0;
#pragma unroll
        for (int q = tid; q < BN*8; q += 256){
            const int r = q>>3, c = q&7;
            cp_async16(wB[s] + r*RSTR + c*16, Wp + (size_t)r*K2 + c*8);
        }
        asm volatile("cp.async.commit_group;\n" ::: "memory");
    };

#pragma unroll
    for (int s=0; s<NS-1; s++){
        if (s < nk) load_tiles(s, s);
        else asm volatile("cp.async.commit_group;\n" ::: "memory");
    }

    const int lr       = lane & 7;
    const int arow_off = ((lane>>3)&1)*8 + lr;
    const int akb      = (lane>>4)*16;
    const int brow_off = ((lane>>4)&1)*8 + lr;
    const int bkb      = ((lane>>3)&1)*16;

    for (int kt = 0; kt < nk; kt++){
        asm volatile("cp.async.wait_group 1;\n" ::: "memory");
        __syncthreads();
        const int pf = kt + NS - 1;
        if (pf < nk) load_tiles(pf % NS, pf);
        else asm volatile("cp.async.commit_group;\n" ::: "memory");

        const uint32_t aBc = aB[kt % NS], wBc = wB[kt % NS];
#pragma unroll
        for (int ks = 0; ks < 4; ks++){
            uint32_t a[2][4];
#pragma unroll
            for (int mt=0; mt<2; mt++){
                const uint32_t addr = aBc + (warp_m*32 + mt*16 + arow_off)*RSTR + ks*32 + akb;
                asm volatile("ldmatrix.sync.aligned.m8n8.x4.shared.b16 {%0,%1,%2,%3}, [%4];"
                    : "=r"(a[mt][0]),"=r"(a[mt][1]),"=r"(a[mt][2]),"=r"(a[mt][3]) : "r"(addr));
            }
            uint32_t b[NTL][2];
#pragma unroll
            for (int ntp=0; ntp<NTL/2; ntp++){
                const uint32_t addr = wBc + (warp_n*WN + ntp*16 + brow_off)*RSTR + ks*32 + bkb;
                asm volatile("ldmatrix.sync.aligned.m8n8.x4.shared.b16 {%0,%1,%2,%3}, [%4];"
                    : "=r"(b[2*ntp][0]),"=r"(b[2*ntp][1]),
                      "=r"(b[2*ntp+1][0]),"=r"(b[2*ntp+1][1]) : "r"(addr));
            }
#pragma unroll
            for (int mt=0; mt<2; mt++)
#pragma unroll
                for (int nt=0; nt<NTL; nt++){
                    asm volatile("mma.sync.aligned.m16n8k16.row.col.f32.f16.f16.f32 "
                        "{%0,%1,%2,%3}, {%4,%5,%6,%7}, {%8,%9}, {%0,%1,%2,%3};"
                        : "+f"(acc[mt][nt][0]),"+f"(acc[mt][nt][1]),
                          "+f"(acc[mt][nt][2]),"+f"(acc[mt][nt][3])
                        : "r"(a[mt][0]),"r"(a[mt][1]),"r"(a[mt][2]),"r"(a[mt][3]),
                          "r"(b[nt][0]),"r"(b[nt][1]));
                }
        }
    }

    const int lr4 = lane>>2, lc2 = (lane&3)*2;
#pragma unroll
    for (int mt=0; mt<2; mt++){
        const int r0 = m0 + warp_m*32 + mt*16 + lr4;
#pragma unroll
        for (int nt=0; nt<NTL; nt++){
            const int col = n0 + warp_n*WN + nt*8 + lc2;
            float b0=0.f, b1=0.f;
            if (BIAS){ b0 = g.bias[col]; b1 = g.bias[col+1]; }
            float2 v0, v1;
            v0.x = acc[mt][nt][0]+b0; v0.y = acc[mt][nt][1]+b1;
            v1.x = acc[mt][nt][2]+b0; v1.y = acc[mt][nt][3]+b1;
            if (SOFTPLUS){
                v0.x = fast_softplus(v0.x); v0.y = fast_softplus(v0.y);
                v1.x = fast_softplus(v1.x); v1.y = fast_softplus(v1.y);
            }
            *(float2*)(g.C + (size_t)r0*N + col)     = v0;
            *(float2*)(g.C + (size_t)(r0+8)*N + col) = v1;
            if (DBLAUG && col < 32){
                __half2* D0 = (__half2*)(g.Daug + (size_t)r0*64);
                __half2* D1 = (__half2*)(g.Daug + (size_t)(r0+8)*64);
                __half h;
                h = __float2half_rn(v0.x); D0[col]   = __halves2half2(h, __float2half_rn(v0.x - __half2float(h)));
                h = __float2half_rn(v0.y); D0[col+1] = __halves2half2(h, __float2half_rn(v0.y - __half2float(h)));
                h = __float2half_rn(v1.x); D1[col]   = __halves2half2(h, __float2half_rn(v1.x - __half2float(h)));
                h = __float2half_rn(v1.y); D1[col+1] = __halves2half2(h, __float2half_rn(v1.y - __half2float(h)));
            }
        }
    }
}

// -------- merged conv, 2 channels/thread: z=0 fused f+r on xz; z=1 g on axz ---------
struct ConvAll {
    const float* Xfr; const float* wf; const float* bf;
    const float* wr;  const float* br;
    __half2* xf; __half2* xr;
    const float* Xg; const float* wg; const float* bg; __half2* xg;
};
#define CCH2 64

__device__ __forceinline__ __half2 mk_pair(float s){
    const __half hh = __float2half_rn(s);
    return __halves2half2(hh, __float2half_rn(s - __half2float(hh)));
}

__global__ void conv_all_kernel(ConvAll P)
{
    const int d0 = (blockIdx.x*128 + threadIdx.x)*2;   // channel pair
    const int bt = blockIdx.y;                          // 0..255
    const int b  = bt >> 6;
    const int t0 = (bt & 63)*CCH2;
    const size_t bL = (size_t)b*L_SEQ;

    if (blockIdx.z == 0){
        const float4 wfA = *(const float4*)(P.wf + d0*4);
        const float4 wfB = *(const float4*)(P.wf + d0*4 + 4);
        const float4 wrA = *(const float4*)(P.wr + d0*4);
        const float4 wrB = *(const float4*)(P.wr + d0*4 + 4);
        const float bfA = P.bf[d0], bfB = P.bf[d0+1];
        const float brA = P.br[d0], brB = P.br[d0+1];
        auto X2 = [&](int i)->float2{
            if (i < 0 || i >= L_SEQ) return make_float2(0.f, 0.f);
            return *(const float2*)(P.Xfr + (bL + i)*(size_t)D_XZ + d0);
        };
        float2 xw[7];
#pragma unroll
        for (int j=0;j<6;j++) xw[j] = X2(t0-3+j);
#pragma unroll 4
        for (int t=t0; t<t0+CCH2; t++){
            xw[6] = X2(t+3);
            const float vfA = fmaf(wfA.x,xw[0].x,fmaf(wfA.y,xw[1].x,fmaf(wfA.z,xw[2].x,fmaf(wfA.w,xw[3].x,bfA))));
            const float vfB = fmaf(wfB.x,xw[0].y,fmaf(wfB.y,xw[1].y,fmaf(wfB.z,xw[2].y,fmaf(wfB.w,xw[3].y,bfB))));
            const float vrA = fmaf(wrA.x,xw[6].x,fmaf(wrA.y,xw[5].x,fmaf(wrA.z,xw[4].x,fmaf(wrA.w,xw[3].x,brA))));
            const float vrB = fmaf(wrB.x,xw[6].y,fmaf(wrB.y,xw[5].y,fmaf(wrB.z,xw[4].y,fmaf(wrB.w,xw[3].y,brB))));
            __align__(8) __half2 of[2] = { mk_pair(siluf_(vfA)), mk_pair(siluf_(vfB)) };
            __align__(8) __half2 orr[2] = { mk_pair(siluf_(vrA)), mk_pair(siluf_(vrB)) };
            *(uint2*)(P.xf + (bL+t)*(size_t)D_INNER + d0) = *(const uint2*)of;
            *(uint2*)(P.xr + (bL + (L_SEQ-1-t))*(size_t)D_INNER + d0) = *(const uint2*)orr;
#pragma unroll
            for (int j=0;j<6;j++) xw[j]=xw[j+1];
        }
    } else {
        const float4 wgA = *(const float4*)(P.wg + d0*4);
        const float4 wgB = *(const float4*)(P.wg + d0*4 + 4);
        const float bgA = P.bg[d0], bgB = P.bg[d0+1];
        auto X2 = [&](int i)->float2{
            if (i < 0) return make_float2(0.f, 0.f);
            return *(const float2*)(P.Xg + (bL + i)*(size_t)D_XZ + d0);
        };
        float2 x0=X2(t0-3), x1=X2(t0-2), x2=X2(t0-1);
#pragma unroll 4
        for (int t=t0; t<t0+CCH2; t++){
            const float2 x3 = X2(t);
            const float vA = fmaf(wgA.x,x0.x,fmaf(wgA.y,x1.x,fmaf(wgA.z,x2.x,fmaf(wgA.w,x3.x,bgA))));
            const float vB = fmaf(wgB.x,x0.y,fmaf(wgB.y,x1.y,fmaf(wgB.z,x2.y,fmaf(wgB.w,x3.y,bgB))));
            __align__(8) __half2 og[2] = { mk_pair(siluf_(vA)), mk_pair(siluf_(vB)) };
            *(uint2*)(P.xg + (bL+t)*(size_t)D_INNER + d0) = *(const uint2*)og;
            x0=x1; x1=x2; x2=x3;
        }
    }
}

// ============== chunked selective scan (dt precomputed in dtproj epilogue) ==========
struct ScanB { const float* U; const __half2* XS2; const float* DBL; const float* XZb;
               const float* Alog; const float* Dp; float* Y;
               float* Hend; float* Hstart; float* Ssum; int rev; };
struct ScanB3 { ScanB s[3]; };

__device__ __forceinline__ void load_A16(const float* Alog, int d, float* a,
                                         float& a0, bool& pw){
#pragma unroll
    for (int n=0;n<16;n++) a[n] = -__expf(Alog[d*16+n]);
    a0 = a[0];
    pw = fabsf(a0) > 1e-20f;
#pragma unroll
    for (int n=0;n<16;n++){
        const float r = a[n]/a0;
        pw = pw && (fabsf(r - (float)(n+1)) < 1e-4f);
    }
}

// Phase A: per-chunk local scan from h=0; stores h_end and S=Σdt. grid(8, B*NCH, 3)
__global__ void scanA_kernel(ScanB3 P)
{
    __shared__ float sB[TCH][16];
    const ScanB S = P.s[blockIdx.z];
    const int tid = threadIdx.x;
    const int d   = blockIdx.x*128 + tid;
    const int b   = blockIdx.y >> 5;
    const int ch  = blockIdx.y & (NCH-1);
    const size_t bL = (size_t)b*L_SEQ;
    const int t0 = ch*TCH;

    float a[16], a0; bool pw;
    load_A16(S.Alog, d, a, a0, pw);

#pragma unroll
    for (int r=0;r<(TCH*16)/(4*128);r++){
        const int slot = tid + r*128;
        const int tt = slot>>2, q = slot&3;
        const float4 v = *(const float4*)(S.DBL + (bL + t0 + tt)*64 + 32 + q*4);
        *(float4*)&sB[tt][q*4] = v;
    }
    __syncthreads();

    __align__(16) float h[16];
#pragma unroll
    for (int n=0;n<16;n++) h[n]=0.f;
    ull* h2 = (ull*)h;
    float Ss = 0.f;

#pragma unroll 2
    for (int tt=0;tt<TCH;tt++){
        const size_t idx = (bL + t0 + tt)*(size_t)D_INNER + d;
        const float dt = S.U[idx];                 // already softplus'd
        const __half2 xp = S.XS2[idx];
        const float xv = __half2float(__low2half(xp)) + __half2float(__high2half(xp));
        Ss += dt;
        const float dtx = dt*xv;
        if (pw){
            const float p  = __expf(dt*a0);
            const float p2 = p*p;
            ull ep = pk2(p, p2);
            const ull estep = pk2(p2, p2);
            const ull dtx2  = pk2(dtx, dtx);
            const ull* Bp = (const ull*)&sB[tt][0];
#pragma unroll
            for (int k=0;k<8;k++){
                ull t1; F2MUL(t1, dtx2, Bp[k]);
                F2FMA(h2[k], ep, h2[k], t1);
                if (k<7) F2MUL(ep, ep, estep);
            }
        } else {
#pragma unroll
            for (int n=0;n<16;n++){
                const float e = __expf(dt*a[n]);
                h[n] = fmaf(e, h[n], dtx*sB[tt][n]);
            }
        }
    }
    float* He = S.Hend + ((size_t)(b*NCH + ch)*D_INNER + d)*16;
#pragma unroll
    for (int q=0;q<4;q++) *(float4*)(He + q*4) = *(float4*)&h[q*4];
    S.Ssum[(size_t)(b*NCH + ch)*D_INNER + d] = Ss;
}

// Phase B: prefix over chunks. grid(8, B, 3), 128 threads
__global__ void scanB_kernel(ScanB3 P)
{
    const ScanB S = P.s[blockIdx.z];
    const int tid = threadIdx.x;
    const int d   = blockIdx.x*128 + tid;
    const int b   = blockIdx.y;

    float a[16], a0; bool pw;
    load_A16(S.Alog, d, a, a0, pw);

    __align__(16) float hs[16];
#pragma unroll
    for (int n=0;n<16;n++) hs[n]=0.f;
    ull* hs2 = (ull*)hs;

    for (int c=0;c<NCH;c++){
        const size_t off = ((size_t)(b*NCH + c)*D_INNER + d)*16;
        float* Hs = S.Hstart + off;
#pragma unroll
        for (int q=0;q<4;q++) *(float4*)(Hs + q*4) = *(float4*)&hs[q*4];
        const float Sc = S.Ssum[(size_t)(b*NCH + c)*D_INNER + d];
        const float* He = S.Hend + off;
        __align__(16) float he[16];
#pragma unroll
        for (int q=0;q<4;q++) *(float4*)&he[q*4] = *(const float4*)(He + q*4);
        if (pw){
            const float p  = __expf(Sc*a0);
            const float p2 = p*p;
            ull ep = pk2(p, p2);
            const ull estep = pk2(p2, p2);
            const ull* he2 = (const ull*)he;
#pragma unroll
            for (int k=0;k<8;k++){
                F2FMA(hs2[k], ep, hs2[k], he2[k]);
                if (k<7) F2MUL(ep, ep, estep);
            }
        } else {
#pragma unroll
            for (int n=0;n<16;n++){
                const float e = __expf(Sc*a[n]);
                hs[n] = fmaf(e, hs[n], he[n]);
            }
        }
    }
}

// Phase C: re-run chunk from true h_start, emit gated y. grid(8, B*NCH, 3)
__global__ void scanC_kernel(ScanB3 P)
{
    __shared__ float sBC[TCH][32];
    const ScanB S = P.s[blockIdx.z];
    const int tid = threadIdx.x;
    const int d   = blockIdx.x*128 + tid;
    const int b   = blockIdx.y >> 5;
    const int ch  = blockIdx.y & (NCH-1);
    const size_t bL = (size_t)b*L_SEQ;
    const int t0 = ch*TCH;

    float a[16], a0; bool pw;
    load_A16(S.Alog, d, a, a0, pw);
    const float Dd = S.Dp[d];

    __align__(16) float h[16];
    {
        const float* Hs = S.Hstart + ((size_t)(b*NCH + ch)*D_INNER + d)*16;
#pragma unroll
        for (int q=0;q<4;q++) *(float4*)&h[q*4] = *(const float4*)(Hs + q*4);
    }
    ull* h2 = (ull*)h;

#pragma unroll
    for (int r=0;r<(TCH*32)/(4*128);r++){
        const int slot = tid + r*128;
        const int tt = slot>>3, q = slot&7;
        const float4 v = *(const float4*)(S.DBL + (bL + t0 + tt)*64 + 32 + q*4);
        *(float4*)&sBC[tt][q*4] = v;
    }
    __syncthreads();

#pragma unroll 2
    for (int tt=0;tt<TCH;tt++){
        const int t = t0+tt;
        const size_t idx = (bL + t)*(size_t)D_INNER + d;
        const float dt = S.U[idx];                 // already softplus'd
        const __half2 xp = S.XS2[idx];
        const float xv = __half2float(__low2half(xp)) + __half2float(__high2half(xp));
        const int lz = S.rev ? (L_SEQ-1-t) : t;
        const float zv = S.XZb[(bL+lz)*(size_t)D_XZ + D_INNER + d];
        const float dtx = dt*xv;
        float y;
        if (pw){
            const float p  = __expf(dt*a0);
            const float p2 = p*p;
            ull ep = pk2(p, p2);
            const ull estep = pk2(p2, p2);
            const ull dtx2  = pk2(dtx, dtx);
            const ull* Bp = (const ull*)&sBC[tt][0];
            const ull* Cp = (const ull*)&sBC[tt][16];
            ull ya0 = 0ull, ya1 = 0ull;
#pragma unroll
            for (int k=0;k<8;k++){
                ull t1; F2MUL(t1, dtx2, Bp[k]);
                F2FMA(h2[k], ep, h2[k], t1);
                if (k & 1) { F2FMA(ya1, h2[k], Cp[k], ya1); }
                else       { F2FMA(ya0, h2[k], Cp[k], ya0); }
                if (k<7) F2MUL(ep, ep, estep);
            }
            float s0,s1,s2,s3;
            upk2(ya0, s0, s1); upk2(ya1, s2, s3);
            y = (s0+s1) + (s2+s3);
        } else {
            float ya[4] = {0.f,0.f,0.f,0.f};
#pragma unroll
            for (int n=0;n<16;n++){
                const float e = __expf(dt*a[n]);
                h[n] = fmaf(e, h[n], dtx*sBC[tt][n]);
                ya[n&3] = fmaf(h[n], sBC[tt][16+n], ya[n&3]);
            }
            y = (ya[0]+ya[1]) + (ya[2]+ya[3]);
        }
        S.Y[idx] = (y + Dd*xv) * siluf_(zv);
    }
}

// ---------------- gated combine -> interleaved half2 --------------------------------
__global__ void combine_kernel(const float* __restrict__ yf, const float* __restrict__ yr,
                               const float* __restrict__ yg, __half2* __restrict__ o)
{
    const size_t i = (size_t)blockIdx.x*256 + threadIdx.x;
    const int d = (int)(i % D_INNER);
    const size_t rr = i / D_INNER;
    const int l = (int)(rr % L_SEQ);
    const int b = (int)(rr / L_SEQ);
    const size_t ridx = ((size_t)b*L_SEQ + (L_SEQ-1-l))*(size_t)D_INNER + d;
    const float v = (yf[i] + yr[ridx]) * siluf_(yg[i]);
    const __half hh = __float2half_rn(v);
    o[rr*(size_t)D_INNER + d] = __halves2half2(hh, __float2half_rn(v - __half2float(hh)));
}

// ------------------------------- host driver ----------------------------------------
extern "C" void kernel_launch(void* const* d_in, const int* in_sizes, int n_in,
                              void* d_out, int out_size)
{
    const float* H    = (const float*)d_in[0];
    const float* AH   = (const float*)d_in[1];
    const float* Winp = (const float*)d_in[2];
    const float* Wing = (const float*)d_in[3];
    const float* convw[3] = { (const float*)d_in[4], (const float*)d_in[6], (const float*)d_in[8] };
    const float* convb[3] = { (const float*)d_in[5], (const float*)d_in[7], (const float*)d_in[9] };
    const float* xproj[3] = { (const float*)d_in[10], (const float*)d_in[11], (const float*)d_in[12] };
    const float* dtw[3]   = { (const float*)d_in[13], (const float*)d_in[15], (const float*)d_in[17] };
    const float* dtb[3]   = { (const float*)d_in[14], (const float*)d_in[16], (const float*)d_in[18] };
    const float* Alog[3]  = { (const float*)d_in[19], (const float*)d_in[20], (const float*)d_in[21] };
    const float* Dp[3]    = { (const float*)d_in[22], (const float*)d_in[23], (const float*)d_in[24] };
    const float* Wout = (const float*)d_in[25];
    float* out = (float*)d_out;

    float *p_xz, *p_axz, *p_u, *p_dbl, *p_y, *p_hend, *p_hstart, *p_ssum;
    __half *p_Haug, *p_AHaug, *p_Wi16, *p_Wg16, *p_xsaug, *p_Xp16;
    __half *p_dtw16, *p_dblaug, *p_Wo16, *p_combaug;
    cudaGetSymbolAddress((void**)&p_xz,     g_xz);
    cudaGetSymbolAddress((void**)&p_axz,    g_axz);
    cudaGetSymbolAddress((void**)&p_u,      g_u);
    cudaGetSymbolAddress((void**)&p_dbl,    g_dbl);
    cudaGetSymbolAddress((void**)&p_y,      g_y);
    cudaGetSymbolAddress((void**)&p_hend,   g_hend);
    cudaGetSymbolAddress((void**)&p_hstart, g_hstart);
    cudaGetSymbolAddress((void**)&p_ssum,   g_ssum);
    cudaGetSymbolAddress((void**)&p_Haug,   g_Haug);
    cudaGetSymbolAddress((void**)&p_AHaug,  g_AHaug);
    cudaGetSymbolAddress((void**)&p_Wi16,   g_Wi16);
    cudaGetSymbolAddress((void**)&p_Wg16,   g_Wg16);
    cudaGetSymbolAddress((void**)&p_xsaug,  g_xsaug);
    cudaGetSymbolAddress((void**)&p_Xp16,   g_Xp16);
    cudaGetSymbolAddress((void**)&p_dtw16,  g_dtw16);
    cudaGetSymbolAddress((void**)&p_dblaug, g_dblaug);
    cudaGetSymbolAddress((void**)&p_Wo16,   g_Wo16);
    cudaGetSymbolAddress((void**)&p_combaug,g_combaug);

    const size_t SXS   = (size_t)NTOK*D_INNER;
    const size_t SDBL  = (size_t)NTOK*64;
    const size_t SXSA  = (size_t)NTOK*2*D_INNER;
    const size_t SXP   = (size_t)64*2*D_INNER;
    const size_t SDTW  = (size_t)D_INNER*2*DT_RANK;
    const size_t SDBLA = (size_t)NTOK*64;
    const size_t SHE   = (size_t)B_SZ*NCH*D_INNER*16;
    const size_t SSS   = (size_t)B_SZ*NCH*D_INNER;

    const int SMEM128 = 3*(128+128)*144;   // 110592 B
    const int SMEM64  = 3*(128+ 64)*144;   //  82944 B
    cudaFuncSetAttribute((const void*)mma_gemm<128,false,false,false>, cudaFuncAttributeMaxDynamicSharedMemorySize, SMEM128);
    cudaFuncSetAttribute((const void*)mma_gemm<128,true,false,true>,   cudaFuncAttributeMaxDynamicSharedMemorySize, SMEM128);
    cudaFuncSetAttribute((const void*)mma_gemm<64,false,true,false>,   cudaFuncAttributeMaxDynamicSharedMemorySize, SMEM64);
    cudaFuncSetAttribute((const void*)mma_gemm<64,false,false,false>,  cudaFuncAttributeMaxDynamicSharedMemorySize, SMEM64);

    // #1: ALL weight conversions (9 jobs, one launch)
    {
        CJobs9 J;
        J.j[0] = { Winp, p_Wi16, (int)((size_t)D_XZ*D_MODEL/4) };
        J.j[1] = { Wing, p_Wg16, (int)((size_t)D_XZ*D_MODEL/4) };
        for (int z=0; z<3; z++){
            J.j[2+z] = { xproj[z], p_Xp16  + z*SXP,  (int)((size_t)64*D_INNER/4) };
            J.j[5+z] = { dtw[z],   p_dtw16 + z*SDTW, (int)((size_t)D_INNER*DT_RANK/4) };
        }
        J.j[8] = { Wout, p_Wo16, (int)((size_t)D_MODEL*D_INNER/4) };
        const int maxb = ((int)((size_t)D_XZ*D_MODEL/4) + 255)/256;   // 1024
        convWdup_multi9<<<dim3(maxb,1,9), 256>>>(J);
    }
    // #2: both activation splits (H, AH) in one launch
    {
        SJobs2 J;
        J.j[0] = { H,  p_Haug };
        J.j[1] = { AH, p_AHaug };
        J.K = D_MODEL; J.n4 = NTOK*D_MODEL/4;
        splitA16_multi<<<dim3((J.n4+255)/256,1,2), 256>>>(J);
    }
    // #3: in-projections
    {
        MG3 P; P.N = D_XZ; P.K2 = 2*D_MODEL;
        P.g[0] = { p_Haug,  p_Wi16, nullptr, p_xz,  nullptr };
        P.g[1] = { p_AHaug, p_Wg16, nullptr, p_axz, nullptr };
        P.g[2] = P.g[0];
        mma_gemm<128,false,false,false><<<dim3(D_XZ/128, NTOK/128, 2), 256, SMEM128>>>(P);
    }
    // #4: ALL convs, 2 channels/thread
    {
        ConvAll P = { p_xz, convw[0], convb[0], convw[1], convb[1],
                      (__half2*)(p_xsaug + 0*SXSA), (__half2*)(p_xsaug + 1*SXSA),
                      p_axz, convw[2], convb[2], (__half2*)(p_xsaug + 2*SXSA) };
        conv_all_kernel<<<dim3(D_INNER/256, B_SZ*(L_SEQ/CCH2), 2), 128>>>(P);
    }
    // #5: x-projection (fused dblaug epilogue)
    {
        MG3 P; P.N = 64; P.K2 = 2*D_INNER;
        for (int z=0; z<3; z++)
            P.g[z] = { p_xsaug + z*SXSA, p_Xp16 + z*SXP, nullptr, p_dbl + z*SDBL, p_dblaug + z*SDBLA };
        mma_gemm<64,false,true,false><<<dim3(1, NTOK/128, 3), 256, SMEM64>>>(P);
    }
    // #6: dt-projection (softplus fused in epilogue -> stores dt directly)
    {
        MG3 P; P.N = D_INNER; P.K2 = 2*DT_RANK;
        for (int z=0; z<3; z++)
            P.g[z] = { p_dblaug + z*SDBLA, p_dtw16 + z*SDTW, dtb[z], p_u + z*SXS, nullptr };
        mma_gemm<128,true,false,true><<<dim3(D_INNER/128, NTOK/128, 3), 256, SMEM128>>>(P);
    }
    // #7-#9: chunked selective scan (A: local, B: prefix, C: emit — all 3 branches)
    {
        ScanB3 P;
        P.s[0] = { p_u + 0*SXS, (const __half2*)(p_xsaug + 0*SXSA), p_dbl + 0*SDBL, p_xz,
                   Alog[0], Dp[0], p_y + 0*SXS, p_hend + 0*SHE, p_hstart + 0*SHE, p_ssum + 0*SSS, 0 };
        P.s[1] = { p_u + 1*SXS, (const __half2*)(p_xsaug + 1*SXSA), p_dbl + 1*SDBL, p_xz,
                   Alog[1], Dp[1], p_y + 1*SXS, p_hend + 1*SHE, p_hstart + 1*SHE, p_ssum + 1*SSS, 1 };
        P.s[2] = { p_u + 2*SXS, (const __half2*)(p_xsaug + 2*SXSA), p_dbl + 2*SDBL, p_axz,
                   Alog[2], Dp[2], p_y + 2*SXS, p_hend + 2*SHE, p_hstart + 2*SHE, p_ssum + 2*SSS, 0 };
        scanA_kernel<<<dim3(D_INNER/128, B_SZ*NCH, 3), 128>>>(P);
        scanB_kernel<<<dim3(D_INNER/128, B_SZ, 3), 128>>>(P);
        scanC_kernel<<<dim3(D_INNER/128, B_SZ*NCH, 3), 128>>>(P);
    }
    // #10: combine
    combine_kernel<<<(unsigned)(SXS/256), 256>>>(p_y + 0*SXS, p_y + 1*SXS, p_y + 2*SXS, (__half2*)p_combaug);
    // #11: out-projection (BN=64)
    {
        MG3 P; P.N = D_MODEL; P.K2 = 2*D_INNER;
        P.g[0] = { p_combaug, p_Wo16, nullptr, out, nullptr };
        P.g[1] = P.g[0]; P.g[2] = P.g[0];
        mma_gemm<64,false,false,false><<<dim3(D_MODEL/64, NTOK/128, 1), 256, SMEM64>>>(P);
    }
    (void)in_sizes; (void)n_in; (void)out_size;
}